// round 17
// baseline (speedup 1.0000x reference)
#include <cuda_runtime.h>
#include <cuda_fp16.h>
#include <cstdint>

// q,k,v: (H=8, B=256, L=128, D=64) fp32 ; pos_bias: (H,1,L,L)
// d_out = [ out (H,B,L,D) | attn (H,B,L,L) ]
// Split-N MMA1 (two 64-col halves through one 32-reg accumulator) + fp16 E packs
// -> ~84 regs -> 3 CTAs/SM. fp16 QKV, bias prep, no-max exp, deferred norm.
#define HH 8
#define BSZ 256
#define LL 128
#define DD 64
#define STR 36   // u32 stride per tile row; 36 % 32 == 4 -> ldmatrix conflict-free

#define OQH 0
#define OKH (OQH + 128 * STR)
#define OVH (OKH + 128 * STR)
#define SMEM_U32 (OVH + 128 * STR)      // 13824 u32 = 55296 B; x3 CTAs = 166KB/SM

// rearranged bias: (h, w, nt, lane) float4 = 32768 float4 (512 KB)
__device__ float4 g_biasr[HH * 8 * 16 * 32];

static __device__ __forceinline__ uint32_t packh(float lo, float hi) {
    uint32_t r;
    asm("cvt.rn.f16x2.f32 %0, %1, %2;" : "=r"(r) : "f"(hi), "f"(lo));
    return r;
}
static __device__ __forceinline__ uint32_t smem_u32(const void* p) {
    uint32_t a;
    asm("{ .reg .u64 t; cvta.to.shared.u64 t, %1; cvt.u32.u64 %0, t; }" : "=r"(a) : "l"(p));
    return a;
}
static __device__ __forceinline__ float ex2f(float x) {
    float r;
    asm("ex2.approx.f32 %0, %1;" : "=f"(r) : "f"(x));
    return r;
}
static __device__ __forceinline__ void stcs2(float* p, float x, float y) {
    asm volatile("st.global.cs.v2.f32 [%0], {%1,%2};" :: "l"(p), "f"(x), "f"(y) : "memory");
}

static __device__ __forceinline__ void mma16816(float* d, const uint32_t* a,
                                                uint32_t b0, uint32_t b1) {
    asm volatile(
        "mma.sync.aligned.m16n8k16.row.col.f32.f16.f16.f32 "
        "{%0,%1,%2,%3}, {%4,%5,%6,%7}, {%8,%9}, {%0,%1,%2,%3};"
        : "+f"(d[0]), "+f"(d[1]), "+f"(d[2]), "+f"(d[3])
        : "r"(a[0]), "r"(a[1]), "r"(a[2]), "r"(a[3]), "r"(b0), "r"(b1));
}

#define LDSM_X4(r, a) \
    asm volatile("ldmatrix.sync.aligned.m8n8.x4.shared.b16 {%0,%1,%2,%3}, [%4];" \
        : "=r"((r)[0]), "=r"((r)[1]), "=r"((r)[2]), "=r"((r)[3]) : "r"(a))
#define LDSM_X4T(r, a) \
    asm volatile("ldmatrix.sync.aligned.m8n8.x4.trans.shared.b16 {%0,%1,%2,%3}, [%4];" \
        : "=r"((r)[0]), "=r"((r)[1]), "=r"((r)[2]), "=r"((r)[3]) : "r"(a))

// ---- prep: 8*bias rearranged into per-(h, warp, nt, lane) fragment order ----
__global__ void bias_prep_kernel(const float* __restrict__ bias)
{
    int tid = blockIdx.x * 256 + threadIdx.x;    // 0..32767
    int lane = tid & 31;
    int nt   = (tid >> 5) & 15;
    int w    = (tid >> 9) & 7;
    int h    = tid >> 12;
    int g = lane >> 2, tq = lane & 3;
    int rA = w * 16 + g, rB = rA + 8, c = 8 * nt + 2 * tq;
    const float* bh = bias + (size_t)h * LL * LL;
    float2 a  = *(const float2*)&bh[rA * LL + c];
    float2 b2 = *(const float2*)&bh[rB * LL + c];
    g_biasr[tid] = make_float4(8.f * a.x, 8.f * a.y, 8.f * b2.x, 8.f * b2.y);
}

__global__ __launch_bounds__(256, 3)
void attn_h16k_kernel(const float* __restrict__ qg_,
                      const float* __restrict__ kg_,
                      const float* __restrict__ vg_,
                      float* __restrict__ outg,
                      float* __restrict__ attng)
{
    extern __shared__ uint32_t smu[];

    const int t = threadIdx.x;
    const int b = blockIdx.x;
    const int h = blockIdx.y;

    const size_t base  = (((size_t)h * BSZ + b) * LL) * DD;
    const size_t abase = (((size_t)h * BSZ + b) * LL) * LL;
    const float4* q4 = (const float4*)(qg_ + base);
    const float4* k4 = (const float4*)(kg_ + base);
    const float4* v4 = (const float4*)(vg_ + base);
    float*        ag = attng + abase;
    float*        og = outg + base;

    const int w = t >> 5, lane = t & 31;
    const int g = lane >> 2, tq = lane & 3;
    const int i0 = w * 16;
    const int rA = i0 + g, rB = i0 + g + 8;

    // ---- Stage Q, K, V as plain fp16, row-major, 36-u32 row stride ----
    #pragma unroll
    for (int it = 0; it < 8; ++it) {
        int idx = t + it * 256;               // 0..2047
        int so = (idx >> 4) * STR + 2 * (idx & 15);
        float4 x = q4[idx];
        *(uint2*)&smu[OQH + so] = make_uint2(packh(x.x, x.y), packh(x.z, x.w));
        x = k4[idx];
        *(uint2*)&smu[OKH + so] = make_uint2(packh(x.x, x.y), packh(x.z, x.w));
        x = v4[idx];
        *(uint2*)&smu[OVH + so] = make_uint2(packh(x.x, x.y), packh(x.z, x.w));
    }

    const float4* br = g_biasr + (((h * 8 + w) * 16) * 32 + lane);

    // ---- per-lane ldmatrix base addresses (bytes) ----
    const uint32_t sb = smem_u32(smu);
    const int lr = lane & 7;
    const int lsel = lane >> 3;               // 0..3
    const uint32_t aQh = sb + 4u * (OQH + (uint32_t)((i0 + (lsel & 1) * 8 + lr) * STR
                                                     + (lsel >> 1) * 4));
    const uint32_t aKb = sb + 4u * (OKH + (uint32_t)(((lane >> 4) * 8 + lr) * STR
                                                     + (lsel & 1) * 4));
    const uint32_t aVb = sb + 4u * (OVH + (uint32_t)(((lsel & 1) * 8 + lr) * STR))
                         + (uint32_t)((lsel >> 1) * 16);

    const float CE = 0.125f * 1.4426950408889634f;   // 0.125 * log2(e)
    uint32_t E[32];                            // fp16 exp packs == MMA2 A-fragments
    float sA = 0.f, sB = 0.f;

    {
        float S[8][4];                         // reused across the two n-halves

        // ======== n-half 0: tiles 0..7 (keys 0..63) ========
        #pragma unroll
        for (int nt = 0; nt < 8; ++nt) {
            float4 bb = __ldg(&br[nt * 32]);
            S[nt][0] = bb.x; S[nt][1] = bb.y; S[nt][2] = bb.z; S[nt][3] = bb.w;
        }
        __syncthreads();

        #pragma unroll
        for (int u = 0; u < 4; ++u) {
            uint32_t qh[4];
            LDSM_X4(qh, aQh + 32u * u);
            #pragma unroll
            for (int ntp = 0; ntp < 4; ++ntp) {
                uint32_t bb[4];
                LDSM_X4(bb, aKb + (uint32_t)(ntp * 16 * STR * 4) + 32u * u);
                mma16816(S[2 * ntp],     qh, bb[0], bb[1]);
                mma16816(S[2 * ntp + 1], qh, bb[2], bb[3]);
            }
        }
        #pragma unroll
        for (int nt = 0; nt < 8; ++nt) {
            float e0 = ex2f(S[nt][0] * CE);
            float e1 = ex2f(S[nt][1] * CE);
            float e2 = ex2f(S[nt][2] * CE);
            float e3 = ex2f(S[nt][3] * CE);
            sA += e0 + e1; sB += e2 + e3;
            E[2 * nt]     = packh(e0, e1);
            E[2 * nt + 1] = packh(e2, e3);
        }

        // ======== n-half 1: tiles 8..15 (keys 64..127) ========
        #pragma unroll
        for (int nt = 0; nt < 8; ++nt) {
            float4 bb = __ldg(&br[(nt + 8) * 32]);
            S[nt][0] = bb.x; S[nt][1] = bb.y; S[nt][2] = bb.z; S[nt][3] = bb.w;
        }
        #pragma unroll
        for (int u = 0; u < 4; ++u) {
            uint32_t qh[4];
            LDSM_X4(qh, aQh + 32u * u);
            #pragma unroll
            for (int ntp = 0; ntp < 4; ++ntp) {
                uint32_t bb[4];
                LDSM_X4(bb, aKb + (uint32_t)((ntp + 4) * 16 * STR * 4) + 32u * u);
                mma16816(S[2 * ntp],     qh, bb[0], bb[1]);
                mma16816(S[2 * ntp + 1], qh, bb[2], bb[3]);
            }
        }
        #pragma unroll
        for (int nt = 0; nt < 8; ++nt) {
            float e0 = ex2f(S[nt][0] * CE);
            float e1 = ex2f(S[nt][1] * CE);
            float e2 = ex2f(S[nt][2] * CE);
            float e3 = ex2f(S[nt][3] * CE);
            sA += e0 + e1; sB += e2 + e3;
            E[16 + 2 * nt]     = packh(e0, e1);
            E[16 + 2 * nt + 1] = packh(e2, e3);
        }
    }

    sA += __shfl_xor_sync(0xffffffffu, sA, 1);
    sA += __shfl_xor_sync(0xffffffffu, sA, 2);
    sB += __shfl_xor_sync(0xffffffffu, sB, 1);
    sB += __shfl_xor_sync(0xffffffffu, sB, 2);
    const float iA = 1.f / sA, iB = 1.f / sB;

    // ---- attn = E * inv (streaming stores, from fp16 packs) ----
    {
        float* aA = ag + (size_t)rA * LL;
        float* aB = ag + (size_t)rB * LL;
        #pragma unroll
        for (int nt = 0; nt < 16; ++nt) {
            float2 eA = __half22float2(*(const __half2*)&E[2 * nt]);
            float2 eB = __half22float2(*(const __half2*)&E[2 * nt + 1]);
            stcs2(&aA[8 * nt + 2 * tq], eA.x * iA, eA.y * iA);
            stcs2(&aB[8 * nt + 2 * tq], eB.x * iB, eB.y * iB);
        }
    }

    // =================== MMA 2: O = E Vh (A-fragments ARE the E packs) ===================
    float O[8][4];
    #pragma unroll
    for (int nt = 0; nt < 8; ++nt)
        O[nt][0] = O[nt][1] = O[nt][2] = O[nt][3] = 0.f;

    #pragma unroll
    for (int u = 0; u < 8; ++u) {             // k-chunks over j (8 x 16)
        #pragma unroll
        for (int nt2 = 0; nt2 < 4; ++nt2) {   // two n8-tiles per ldmatrix.x4.trans
            uint32_t bb[4];
            LDSM_X4T(bb, aVb + (uint32_t)(u * 16 * STR * 4) + (uint32_t)(nt2 * 32));
            mma16816(O[2 * nt2],     &E[4 * u], bb[0], bb[1]);
            mma16816(O[2 * nt2 + 1], &E[4 * u], bb[2], bb[3]);
        }
    }

    // ---- out = O * inv (streaming stores) ----
    {
        float* oA = og + (size_t)rA * DD;
        float* oB = og + (size_t)rB * DD;
        #pragma unroll
        for (int nt = 0; nt < 8; ++nt) {
            stcs2(&oA[8 * nt + 2 * tq], O[nt][0] * iA, O[nt][1] * iA);
            stcs2(&oB[8 * nt + 2 * tq], O[nt][2] * iB, O[nt][3] * iB);
        }
    }
}

extern "C" void kernel_launch(void* const* d_in, const int* in_sizes, int n_in,
                              void* d_out, int out_size)
{
    const float* q    = (const float*)d_in[0];
    const float* k    = (const float*)d_in[1];
    const float* v    = (const float*)d_in[2];
    const float* bias = (const float*)d_in[3];

    float* out  = (float*)d_out;
    float* attn = out + (size_t)HH * BSZ * LL * DD;

    bias_prep_kernel<<<128, 256>>>(bias);

    const size_t smem = (size_t)SMEM_U32 * 4;   // 55296 B
    cudaFuncSetAttribute(attn_h16k_kernel,
                         cudaFuncAttributeMaxDynamicSharedMemorySize, (int)smem);

    dim3 grid(BSZ, HH);
    attn_h16k_kernel<<<grid, 256, smem>>>(q, k, v, out, attn);
}